// round 2
// baseline (speedup 1.0000x reference)
#include <cuda_runtime.h>

// LoraConv2dExperts: out = sum_e p_e * Conv3x1_e(Conv1x3_e(x))
// Shapes: x[16,256,64,64], weight_in[8,8,256,1,3], weight_out[8,256,8,3,1]
// Folded: stage1 conv (CIN=256 -> ER=64, kernel 1x3), stage2 conv (ER=64 -> 256, kernel 3x1, probs folded)

#define B_N   16
#define CIN_N 256
#define COUT_N 256
#define H_N   64
#define W_N   64
#define ER_N  64   // E*R

typedef unsigned long long ull;

// scratch (device globals; no allocation allowed)
__device__ float g_h[B_N * ER_N * H_N * W_N];     // 16 MB intermediate [b][er][y][w]
__device__ float g_W1t[CIN_N * 3 * ER_N];         // [ci][dw][er]
__device__ float g_W2[ER_N * COUT_N * 3];         // [er][co][dh], probs folded

__device__ __forceinline__ void ffma2(ull &d, ull a, ull b) {
    asm("fma.rn.f32x2 %0, %1, %2, %0;" : "+l"(d) : "l"(a), "l"(b));
}
__device__ __forceinline__ ull bcast2(float v) {
    ull r; asm("mov.b64 %0, {%1, %2};" : "=l"(r) : "f"(v), "f"(v)); return r;
}
__device__ __forceinline__ float2 lohi(ull v) {
    float2 r; asm("mov.b64 {%0, %1}, %2;" : "=f"(r.x), "=f"(r.y) : "l"(v)); return r;
}

// ---------------------------------------------------------------------------
// Prep: transpose W1 -> [ci][dw][er]; fold probs into W2 -> [er][co][dh]
// ---------------------------------------------------------------------------
__global__ void prep_kernel(const float* __restrict__ win,
                            const float* __restrict__ wout,
                            const float* __restrict__ probs) {
    int idx = blockIdx.x * 256 + threadIdx.x;
    if (idx >= ER_N * 768) return;   // 49152
    int er  = idx / 768;
    int rem = idx - er * 768;        // ci*3+dw  (also co*3+dh for W2)
    // W1t: win flat layout is exactly [er][ci][dw] = er*768 + ci*3 + dw
    g_W1t[rem * ER_N + er] = win[idx];
    // W2: wout flat layout [e][co][r][dh]
    int co = rem / 3, dh = rem - co * 3;
    int e = er >> 3, r = er & 7;
    g_W2[idx] = probs[e] * wout[(((e << 8) + co) * 8 + r) * 3 + dh];
}

// ---------------------------------------------------------------------------
// Stage 1: h[b,er,y,w] = sum_ci sum_dw W1[er,ci,dw] * x[b,ci,y,w+dw-1]
// grid = B*(H/8) = 128 blocks, 256 threads.
// thread tile: 8 er (4 f32x2 pairs) x 16 w, one y row.
// ---------------------------------------------------------------------------
#define S1_XS_FLOATS (32 * 8 * 68)   // [cc][yy][68] padded row
#define S1_WS_FLOATS (32 * 3 * 64)   // [cc][dw][er]
#define S1_SMEM ((S1_XS_FLOATS + S1_WS_FLOATS) * 4)

__global__ __launch_bounds__(256, 1)
void stage1_kernel(const float* __restrict__ x) {
    extern __shared__ float sm[];
    float* xs = sm;                  // [32][8][68]
    float* ws = sm + S1_XS_FLOATS;   // [32][3][64]

    const int tid = threadIdx.x;
    const int b  = blockIdx.x >> 3;
    const int y0 = (blockIdx.x & 7) << 3;
    const int w0  = (tid & 3) << 4;          // 0,16,32,48
    const int er0 = ((tid >> 2) & 7) << 3;   // 0..56
    const int yy  = tid >> 5;                // 0..7 (one per warp)

    // zero the pad columns once (row `tid` of the 256 rows)
    {
        float* row = xs + tid * 68;
        row[0] = 0.f; row[65] = 0.f; row[66] = 0.f; row[67] = 0.f;
    }

    ull acc[4][16];
#pragma unroll
    for (int i = 0; i < 4; i++)
#pragma unroll
        for (int j = 0; j < 16; j++) acc[i][j] = 0ull;

    for (int ci0 = 0; ci0 < CIN_N; ci0 += 32) {
        __syncthreads();
        // load x chunk: 32 ci x 8 rows x 64 w
        for (int t = tid; t < 4096; t += 256) {
            int cc = t >> 7, rem = t & 127, yyl = rem >> 4, v = rem & 15;
            const float4 val = *(const float4*)(x +
                (((((b << 8) + ci0 + cc) << 6) + (y0 + yyl)) << 6) + (v << 2));
            float* dst = xs + (t >> 4) * 68 + 1 + (v << 2);
            dst[0] = val.x; dst[1] = val.y; dst[2] = val.z; dst[3] = val.w;
        }
        // load weight chunk (contiguous, vectorized)
        for (int t = tid; t < 1536; t += 256)
            *(float4*)(ws + (t << 2)) = *(const float4*)(g_W1t + ci0 * 192 + (t << 2));
        __syncthreads();

#pragma unroll 1
        for (int cc = 0; cc < 32; cc++) {
            // hoist ALL smem loads for this cc up front: maximizes LDS MLP,
            // shrinks short-scoreboard exposure before the FFMA2 burst.
            const float* xrow = xs + (cc * 8 + yy) * 68 + w0;
            float xv[18];
#pragma unroll
            for (int t = 0; t < 18; t++) xv[t] = xrow[t];
            const float* wr = ws + cc * 192 + er0;
            ull wp[3][4];
#pragma unroll
            for (int dw = 0; dw < 3; dw++) {
                wp[dw][0] = *(const ull*)(wr + dw * 64 + 0);
                wp[dw][1] = *(const ull*)(wr + dw * 64 + 2);
                wp[dw][2] = *(const ull*)(wr + dw * 64 + 4);
                wp[dw][3] = *(const ull*)(wr + dw * 64 + 6);
            }
#pragma unroll
            for (int dw = 0; dw < 3; dw++) {
#pragma unroll
                for (int j = 0; j < 16; j++) {
                    ull xb = bcast2(xv[j + dw]);
                    ffma2(acc[0][j], wp[dw][0], xb);
                    ffma2(acc[1][j], wp[dw][1], xb);
                    ffma2(acc[2][j], wp[dw][2], xb);
                    ffma2(acc[3][j], wp[dw][3], xb);
                }
            }
        }
    }

    // store: unpack er-pairs into two rows, 4x float4 each
    const int ybase = y0 + yy;
#pragma unroll
    for (int i = 0; i < 4; i++) {
        float lo[16], hi[16];
#pragma unroll
        for (int j = 0; j < 16; j++) { float2 p = lohi(acc[i][j]); lo[j] = p.x; hi[j] = p.y; }
        float* r0 = g_h + (((b * ER_N + er0 + 2 * i) * H_N) + ybase) * W_N + w0;
        float* r1 = r0 + H_N * W_N;
#pragma unroll
        for (int v = 0; v < 4; v++) {
            *(float4*)(r0 + 4 * v) = make_float4(lo[4*v], lo[4*v+1], lo[4*v+2], lo[4*v+3]);
            *(float4*)(r1 + 4 * v) = make_float4(hi[4*v], hi[4*v+1], hi[4*v+2], hi[4*v+3]);
        }
    }
}

// ---------------------------------------------------------------------------
// Stage 2: out[b,co,y,w] = sum_er sum_dh W2[er,co,dh] * h[b,er,y+dh-1,w]
// grid = B * (H/2) = 512 blocks, 256 threads.
// thread tile: 8 co x 16 w (8 f32x2 pairs along w), one y row.
// ---------------------------------------------------------------------------
#define S2_HS_FLOATS (64 * 4 * 64)   // [er][row 0..3][w], rows = y0-1..y0+2
#define S2_WS_FLOATS (16 * 768)      // [erl][co*3+dh]
#define S2_SMEM ((S2_HS_FLOATS + S2_WS_FLOATS) * 4)

__global__ __launch_bounds__(256, 1)
void stage2_kernel(float* __restrict__ out) {
    extern __shared__ float sm[];
    float* hs  = sm;                 // [64][4][64]
    float* ws2 = sm + S2_HS_FLOATS;  // [16][768]

    const int tid = threadIdx.x;
    const int b  = blockIdx.x >> 5;
    const int y0 = (blockIdx.x & 31) << 1;
    const int w0  = (tid & 3) << 4;
    const int co0 = ((tid >> 2) & 31) << 3;
    const int yy  = tid >> 7;        // 0..1

    // load h rows y0-1 .. y0+2 (zero-pad at borders)
    for (int t = tid; t < 4096; t += 256) {
        int er = t >> 6, rem = t & 63, r = rem >> 4, v = rem & 15;
        int gy = y0 - 1 + r;
        float4 val = make_float4(0.f, 0.f, 0.f, 0.f);
        if ((unsigned)gy < 64u)
            val = *(const float4*)(g_h + (((b * ER_N + er) * H_N) + gy) * W_N + (v << 2));
        *(float4*)(hs + (er * 4 + r) * 64 + (v << 2)) = val;
    }

    ull acc[8][8];
#pragma unroll
    for (int i = 0; i < 8; i++)
#pragma unroll
        for (int j = 0; j < 8; j++) acc[i][j] = 0ull;

    for (int ec = 0; ec < ER_N; ec += 16) {
        __syncthreads();
        for (int t = tid; t < 3072; t += 256)
            *(float4*)(ws2 + (t << 2)) = *(const float4*)(g_W2 + ec * 768 + (t << 2));
        __syncthreads();

#pragma unroll 1
        for (int erl = 0; erl < 16; erl++) {
            const int er = ec + erl;
            const float* wr = ws2 + erl * 768 + co0 * 3;
            // hoist h-row pairs for all 3 dh (rows er*4 + yy + 0..2)
            ull hp[3][8];
#pragma unroll
            for (int dh = 0; dh < 3; dh++) {
                const float* hrow = hs + (er * 4 + yy + dh) * 64 + w0;
#pragma unroll
                for (int j = 0; j < 8; j++)
                    hp[dh][j] = *(const ull*)(hrow + 2 * j);
            }
#pragma unroll
            for (int i = 0; i < 8; i++) {
#pragma unroll
                for (int dh = 0; dh < 3; dh++) {
                    ull wb = bcast2(wr[i * 3 + dh]);
#pragma unroll
                    for (int j = 0; j < 8; j++)
                        ffma2(acc[i][j], wb, hp[dh][j]);
                }
            }
        }
    }

    const int y = y0 + yy;
#pragma unroll
    for (int i = 0; i < 8; i++) {
        float* r = out + ((b * COUT_N + co0 + i) * H_N + y) * W_N + w0;
#pragma unroll
        for (int v = 0; v < 4; v++) {
            float2 pa = lohi(acc[i][2 * v]);
            float2 pb = lohi(acc[i][2 * v + 1]);
            *(float4*)(r + 4 * v) = make_float4(pa.x, pa.y, pb.x, pb.y);
        }
    }
}

// ---------------------------------------------------------------------------
extern "C" void kernel_launch(void* const* d_in, const int* in_sizes, int n_in,
                              void* d_out, int out_size) {
    (void)in_sizes; (void)n_in; (void)out_size;
    const float* x     = (const float*)d_in[0];
    const float* probs = (const float*)d_in[1];
    const float* win   = (const float*)d_in[2];
    const float* wout  = (const float*)d_in[3];
    float* out = (float*)d_out;

    cudaFuncSetAttribute(stage1_kernel, cudaFuncAttributeMaxDynamicSharedMemorySize, S1_SMEM);
    cudaFuncSetAttribute(stage2_kernel, cudaFuncAttributeMaxDynamicSharedMemorySize, S2_SMEM);

    prep_kernel<<<192, 256>>>(win, wout, probs);
    stage1_kernel<<<B_N * (H_N / 8), 256, S1_SMEM>>>(x);
    stage2_kernel<<<B_N * (H_N / 2), 256, S2_SMEM>>>(out);
}

// round 3
// speedup vs baseline: 1.0015x; 1.0015x over previous
#include <cuda_runtime.h>

// LoraConv2dExperts: out = sum_e p_e * Conv3x1_e(Conv1x3_e(x))
// Shapes: x[16,256,64,64], weight_in[8,8,256,1,3], weight_out[8,256,8,3,1]
// Folded: stage1 conv (CIN=256 -> ER=64, kernel 1x3), stage2 conv (ER=64 -> 256, kernel 3x1, probs folded)

#define B_N   16
#define CIN_N 256
#define COUT_N 256
#define H_N   64
#define W_N   64
#define ER_N  64   // E*R

typedef unsigned long long ull;

// scratch (device globals; no allocation allowed)
__device__ float g_h[B_N * ER_N * H_N * W_N];     // 16 MB intermediate [b][er][y][w]
__device__ float g_W1t[CIN_N * 3 * ER_N];         // [ci][dw][er]
__device__ float g_W2[ER_N * COUT_N * 3];         // [er][co][dh], probs folded

__device__ __forceinline__ void ffma2(ull &d, ull a, ull b) {
    asm("fma.rn.f32x2 %0, %1, %2, %0;" : "+l"(d) : "l"(a), "l"(b));
}
__device__ __forceinline__ ull bcast2(float v) {
    ull r; asm("mov.b64 %0, {%1, %2};" : "=l"(r) : "f"(v), "f"(v)); return r;
}
__device__ __forceinline__ float2 lohi(ull v) {
    float2 r; asm("mov.b64 {%0, %1}, %2;" : "=f"(r.x), "=f"(r.y) : "l"(v)); return r;
}

// ---------------------------------------------------------------------------
// Prep: transpose W1 -> [ci][dw][er]; fold probs into W2 -> [er][co][dh]
// ---------------------------------------------------------------------------
__global__ void prep_kernel(const float* __restrict__ win,
                            const float* __restrict__ wout,
                            const float* __restrict__ probs) {
    int idx = blockIdx.x * 256 + threadIdx.x;
    if (idx >= ER_N * 768) return;   // 49152
    int er  = idx / 768;
    int rem = idx - er * 768;        // ci*3+dw  (also co*3+dh for W2)
    // W1t: win flat layout is exactly [er][ci][dw] = er*768 + ci*3 + dw
    g_W1t[rem * ER_N + er] = win[idx];
    // W2: wout flat layout [e][co][r][dh]
    int co = rem / 3, dh = rem - co * 3;
    int e = er >> 3, r = er & 7;
    g_W2[idx] = probs[e] * wout[(((e << 8) + co) * 8 + r) * 3 + dh];
}

// ---------------------------------------------------------------------------
// Stage 1: h[b,er,y,w] = sum_ci sum_dw W1[er,ci,dw] * x[b,ci,y,w+dw-1]
// grid = B*(H/8) = 128 blocks, 256 threads.
// thread tile: 8 er (4 f32x2 pairs) x 16 w, one y row.
// ---------------------------------------------------------------------------
#define S1_XS_FLOATS (32 * 8 * 68)   // [cc][yy][68] padded row
#define S1_WS_FLOATS (32 * 3 * 64)   // [cc][dw][er]
#define S1_SMEM ((S1_XS_FLOATS + S1_WS_FLOATS) * 4)

__global__ __launch_bounds__(256, 1)
void stage1_kernel(const float* __restrict__ x) {
    extern __shared__ float sm[];
    float* xs = sm;                  // [32][8][68]
    float* ws = sm + S1_XS_FLOATS;   // [32][3][64]

    const int tid = threadIdx.x;
    const int b  = blockIdx.x >> 3;
    const int y0 = (blockIdx.x & 7) << 3;
    const int w0  = (tid & 3) << 4;          // 0,16,32,48
    const int er0 = ((tid >> 2) & 7) << 3;   // 0..56
    const int yy  = tid >> 5;                // 0..7 (one per warp)

    // zero the pad columns once (row `tid` of the 256 rows)
    {
        float* row = xs + tid * 68;
        row[0] = 0.f; row[65] = 0.f; row[66] = 0.f; row[67] = 0.f;
    }

    ull acc[4][16];
#pragma unroll
    for (int i = 0; i < 4; i++)
#pragma unroll
        for (int j = 0; j < 16; j++) acc[i][j] = 0ull;

    for (int ci0 = 0; ci0 < CIN_N; ci0 += 32) {
        __syncthreads();
        // load x chunk: 32 ci x 8 rows x 64 w
        for (int t = tid; t < 4096; t += 256) {
            int cc = t >> 7, rem = t & 127, yyl = rem >> 4, v = rem & 15;
            const float4 val = *(const float4*)(x +
                (((((b << 8) + ci0 + cc) << 6) + (y0 + yyl)) << 6) + (v << 2));
            float* dst = xs + (t >> 4) * 68 + 1 + (v << 2);
            dst[0] = val.x; dst[1] = val.y; dst[2] = val.z; dst[3] = val.w;
        }
        // load weight chunk (contiguous, vectorized)
        for (int t = tid; t < 1536; t += 256)
            *(float4*)(ws + (t << 2)) = *(const float4*)(g_W1t + ci0 * 192 + (t << 2));
        __syncthreads();

#pragma unroll 1
        for (int cc = 0; cc < 32; cc++) {
            // hoist ALL smem loads for this cc up front: maximizes LDS MLP,
            // shrinks short-scoreboard exposure before the FFMA2 burst.
            const float* xrow = xs + (cc * 8 + yy) * 68 + w0;
            float xv[18];
#pragma unroll
            for (int t = 0; t < 18; t++) xv[t] = xrow[t];
            const float* wr = ws + cc * 192 + er0;
            ull wp[3][4];
#pragma unroll
            for (int dw = 0; dw < 3; dw++) {
                wp[dw][0] = *(const ull*)(wr + dw * 64 + 0);
                wp[dw][1] = *(const ull*)(wr + dw * 64 + 2);
                wp[dw][2] = *(const ull*)(wr + dw * 64 + 4);
                wp[dw][3] = *(const ull*)(wr + dw * 64 + 6);
            }
#pragma unroll
            for (int dw = 0; dw < 3; dw++) {
#pragma unroll
                for (int j = 0; j < 16; j++) {
                    ull xb = bcast2(xv[j + dw]);
                    ffma2(acc[0][j], wp[dw][0], xb);
                    ffma2(acc[1][j], wp[dw][1], xb);
                    ffma2(acc[2][j], wp[dw][2], xb);
                    ffma2(acc[3][j], wp[dw][3], xb);
                }
            }
        }
    }

    // store: unpack er-pairs into two rows, 4x float4 each
    const int ybase = y0 + yy;
#pragma unroll
    for (int i = 0; i < 4; i++) {
        float lo[16], hi[16];
#pragma unroll
        for (int j = 0; j < 16; j++) { float2 p = lohi(acc[i][j]); lo[j] = p.x; hi[j] = p.y; }
        float* r0 = g_h + (((b * ER_N + er0 + 2 * i) * H_N) + ybase) * W_N + w0;
        float* r1 = r0 + H_N * W_N;
#pragma unroll
        for (int v = 0; v < 4; v++) {
            *(float4*)(r0 + 4 * v) = make_float4(lo[4*v], lo[4*v+1], lo[4*v+2], lo[4*v+3]);
            *(float4*)(r1 + 4 * v) = make_float4(hi[4*v], hi[4*v+1], hi[4*v+2], hi[4*v+3]);
        }
    }
}

// ---------------------------------------------------------------------------
// Stage 2: out[b,co,y,w] = sum_er sum_dh W2[er,co,dh] * h[b,er,y+dh-1,w]
// grid = B * (H/2) = 512 blocks, 256 threads.
// thread tile: 8 co x 16 w (8 f32x2 pairs along w), one y row.
// ---------------------------------------------------------------------------
#define S2_HS_FLOATS (64 * 4 * 64)   // [er][row 0..3][w], rows = y0-1..y0+2
#define S2_WS_FLOATS (16 * 768)      // [erl][co*3+dh]
#define S2_SMEM ((S2_HS_FLOATS + S2_WS_FLOATS) * 4)

__global__ __launch_bounds__(256, 1)
void stage2_kernel(float* __restrict__ out) {
    extern __shared__ float sm[];
    float* hs  = sm;                 // [64][4][64]
    float* ws2 = sm + S2_HS_FLOATS;  // [16][768]

    const int tid = threadIdx.x;
    const int b  = blockIdx.x >> 5;
    const int y0 = (blockIdx.x & 31) << 1;
    const int w0  = (tid & 3) << 4;
    const int co0 = ((tid >> 2) & 31) << 3;
    const int yy  = tid >> 7;        // 0..1

    // load h rows y0-1 .. y0+2 (zero-pad at borders)
    for (int t = tid; t < 4096; t += 256) {
        int er = t >> 6, rem = t & 63, r = rem >> 4, v = rem & 15;
        int gy = y0 - 1 + r;
        float4 val = make_float4(0.f, 0.f, 0.f, 0.f);
        if ((unsigned)gy < 64u)
            val = *(const float4*)(g_h + (((b * ER_N + er) * H_N) + gy) * W_N + (v << 2));
        *(float4*)(hs + (er * 4 + r) * 64 + (v << 2)) = val;
    }

    ull acc[8][8];
#pragma unroll
    for (int i = 0; i < 8; i++)
#pragma unroll
        for (int j = 0; j < 8; j++) acc[i][j] = 0ull;

    for (int ec = 0; ec < ER_N; ec += 16) {
        __syncthreads();
        for (int t = tid; t < 3072; t += 256)
            *(float4*)(ws2 + (t << 2)) = *(const float4*)(g_W2 + ec * 768 + (t << 2));
        __syncthreads();

#pragma unroll 1
        for (int erl = 0; erl < 16; erl++) {
            const int er = ec + erl;
            const float* wr = ws2 + erl * 768 + co0 * 3;
            // hoist h-row pairs for all 3 dh (rows er*4 + yy + 0..2)
            ull hp[3][8];
#pragma unroll
            for (int dh = 0; dh < 3; dh++) {
                const float* hrow = hs + (er * 4 + yy + dh) * 64 + w0;
#pragma unroll
                for (int j = 0; j < 8; j++)
                    hp[dh][j] = *(const ull*)(hrow + 2 * j);
            }
#pragma unroll
            for (int i = 0; i < 8; i++) {
#pragma unroll
                for (int dh = 0; dh < 3; dh++) {
                    ull wb = bcast2(wr[i * 3 + dh]);
#pragma unroll
                    for (int j = 0; j < 8; j++)
                        ffma2(acc[i][j], wb, hp[dh][j]);
                }
            }
        }
    }

    const int y = y0 + yy;
#pragma unroll
    for (int i = 0; i < 8; i++) {
        float* r = out + ((b * COUT_N + co0 + i) * H_N + y) * W_N + w0;
#pragma unroll
        for (int v = 0; v < 4; v++) {
            float2 pa = lohi(acc[i][2 * v]);
            float2 pb = lohi(acc[i][2 * v + 1]);
            *(float4*)(r + 4 * v) = make_float4(pa.x, pa.y, pb.x, pb.y);
        }
    }
}

// ---------------------------------------------------------------------------
extern "C" void kernel_launch(void* const* d_in, const int* in_sizes, int n_in,
                              void* d_out, int out_size) {
    (void)in_sizes; (void)n_in; (void)out_size;
    const float* x     = (const float*)d_in[0];
    const float* probs = (const float*)d_in[1];
    const float* win   = (const float*)d_in[2];
    const float* wout  = (const float*)d_in[3];
    float* out = (float*)d_out;

    cudaFuncSetAttribute(stage1_kernel, cudaFuncAttributeMaxDynamicSharedMemorySize, S1_SMEM);
    cudaFuncSetAttribute(stage2_kernel, cudaFuncAttributeMaxDynamicSharedMemorySize, S2_SMEM);

    prep_kernel<<<192, 256>>>(win, wout, probs);
    stage1_kernel<<<B_N * (H_N / 8), 256, S1_SMEM>>>(x);
    stage2_kernel<<<B_N * (H_N / 2), 256, S2_SMEM>>>(out);
}

// round 15
// speedup vs baseline: 1.9146x; 1.9119x over previous
#include <cuda_runtime.h>
#include <cuda_bf16.h>

typedef unsigned int u32; typedef unsigned long long ull;

// out = sum_e p_e * Conv3x1_e(Conv1x3_e(x));  x[16,256,64,64] fp32
// Baseline-PTX tensor path (compute_103-safe): ldmatrix + mma.sync bf16.
// Stage1: h[64er][64w] per (b,y): K=768 (4 chunks of 192). bf16 hi/lo 3-term split.
// Stage2: out[256co][64w] per (b,y): K=192 (er*3+dh), 4 co-blocks of 64.
__device__ __align__(16) __nv_bfloat16 g_W1img[4][128*200]; // [chunk][64 hi rows + 64 lo rows][200(192+pad)]
__device__ __align__(16) __nv_bfloat16 g_W2img[4][128*200]; // [co-block][64 hi + 64 lo][200]
__device__ __align__(16) __nv_bfloat16 g_hh[16*64*64*64];   // h hi [b][er][y][w]
__device__ __align__(16) __nv_bfloat16 g_hl[16*64*64*64];   // h lo

__device__ __forceinline__ u32 smaddr(const void* p){
    u32 a; asm("{ .reg .u64 t; cvta.to.shared.u64 t, %1; cvt.u32.u64 %0, t; }":"=r"(a):"l"(p)); return a;
}
__device__ __forceinline__ void ldsm4(u32* r, u32 a){
    asm volatile("ldmatrix.sync.aligned.m8n8.x4.shared.b16 {%0,%1,%2,%3},[%4];"
        :"=r"(r[0]),"=r"(r[1]),"=r"(r[2]),"=r"(r[3]):"r"(a));
}
__device__ __forceinline__ void ldsm4t(u32* r, u32 a){
    asm volatile("ldmatrix.sync.aligned.m8n8.x4.trans.shared.b16 {%0,%1,%2,%3},[%4];"
        :"=r"(r[0]),"=r"(r[1]),"=r"(r[2]),"=r"(r[3]):"r"(a));
}
__device__ __forceinline__ void mma_bf16(float* d, const u32* a, u32 b0, u32 b1){
    asm volatile("mma.sync.aligned.m16n8k16.row.col.f32.bf16.bf16.f32 "
        "{%0,%1,%2,%3},{%4,%5,%6,%7},{%8,%9},{%0,%1,%2,%3};"
        :"+f"(d[0]),"+f"(d[1]),"+f"(d[2]),"+f"(d[3])
        :"r"(a[0]),"r"(a[1]),"r"(a[2]),"r"(a[3]),"r"(b0),"r"(b1));
}
__device__ __forceinline__ u32 pack2(float a,float b){
    __nv_bfloat162 t=__floats2bfloat162_rn(a,b); return *(u32*)&t;
}
__device__ __forceinline__ float bhi(float v){ return __bfloat162float(__float2bfloat16(v)); }

// ---------------- prep: A images (row-major, 200-elem padded rows) ----------
__global__ void prep_w1(const float* __restrict__ win){
    int idx=blockIdx.x*256+threadIdx.x; if(idx>=98304) return;
    int c=idx/24576, rem=idx%24576, m=rem/192, k=rem%192, er=m&63;
    float v=win[er*768 + c*192 + k];                 // win flat = [er][ci][dw]
    float o=(m<64)? v : (v-bhi(v));
    g_W1img[c][m*200+k]=__float2bfloat16(o);
}
__global__ void prep_w2(const float* __restrict__ wout,const float* __restrict__ probs){
    int idx=blockIdx.x*256+threadIdx.x; if(idx>=98304) return;
    int cb=idx/24576, rem=idx%24576, m=rem/192, k=rem%192;
    int er=k/3, dh=k-er*3, e=er>>3, r=er&7, co=cb*64+(m&63);
    float v=probs[e]*wout[((e*256+co)*8+r)*3+dh];    // wout flat = [e][co][r][dh]
    float o=(m<64)? v : (v-bhi(v));
    g_W2img[cb][m*200+k]=__float2bfloat16(o);
}

// smem: As [128][200] bf16 @0 (51200 B); Bs [4 tiles: yy*2+p][192 k][144 B] @51200 (110592 B)
#define S_SMEM 161792

// ---------------- stage 1 ----------------
__global__ __launch_bounds__(256,1) void stage1(const float* __restrict__ x){
    extern __shared__ char sm[];
    __nv_bfloat16* As=(__nv_bfloat16*)sm;
    char* Bs=sm+51200;
    const int tid=threadIdx.x, wid=tid>>5, lane=tid&31;
    const int b=blockIdx.x>>5, y0=(blockIdx.x&31)<<1;
    const int yyw=wid>>2, mh=(wid>>1)&1, nh=wid&1;
    const u32 sA=smaddr(As), sB=smaddr(Bs);
    const int lr=lane&7, ls=lane>>3;
    const u32 aLane=(u32)(((ls&1)*8+lr)*400+(ls>>1)*16);
    const u32 bLane=(u32)(((ls&1)*8+lr)*144+(ls>>1)*16);

    float acc[2][4][4];
#pragma unroll
    for(int i=0;i<2;i++)
#pragma unroll
        for(int j=0;j<4;j++){acc[i][j][0]=0;acc[i][j][1]=0;acc[i][j][2]=0;acc[i][j][3]=0;}

    for(int c=0;c<4;c++){
        __syncthreads();
        { const uint4* src=(const uint4*)g_W1img[c]; uint4* dst=(uint4*)As;
          for(int i=tid;i<3200;i+=256) dst[i]=src[i]; }
        // B build: Bt[yy*2+p][k=3*ci+dw][w] = split(x[ci_g][y][w+dw-1])
#pragma unroll
        for(int i=0;i<8;i++){
            int t=tid+256*i, ci=t>>5, yy=(t>>4)&1, v4=t&15;
            const float4 v=*(const float4*)(x + (((size_t)(b*256+c*64+ci)*64)+(y0+yy))*64 + v4*4);
            float xl=__shfl_up_sync(0xffffffffu, v.w, 1);
            float xr=__shfl_down_sync(0xffffffffu, v.x, 1);
            if(v4==0) xl=0.f;
            if(v4==15) xr=0.f;
            float a6[6]={xl,v.x,v.y,v.z,v.w,xr}, h6[6], l6[6];
#pragma unroll
            for(int j=0;j<6;j++){ h6[j]=bhi(a6[j]); l6[j]=a6[j]-h6[j]; }
            char* th=Bs + (yy*2+0)*27648 + (3*ci)*144 + v4*8;
            char* tl=Bs + (yy*2+1)*27648 + (3*ci)*144 + v4*8;
#pragma unroll
            for(int dw=0;dw<3;dw++){
                ull ph=(ull)pack2(h6[dw],h6[dw+1]) | ((ull)pack2(h6[dw+2],h6[dw+3])<<32);
                ull pl=(ull)pack2(l6[dw],l6[dw+1]) | ((ull)pack2(l6[dw+2],l6[dw+3])<<32);
                *(ull*)(th+dw*144)=ph;
                *(ull*)(tl+dw*144)=pl;
            }
        }
        __syncthreads();
        const u32 aH=sA + (u32)(mh*32*400) + aLane;
        const u32 aL=aH + 64u*400u;
        const u32 bH=sB + (u32)((yyw*2+0)*27648 + nh*64) + bLane;
        const u32 bL=sB + (u32)((yyw*2+1)*27648 + nh*64) + bLane;
#pragma unroll 1
        for(int ks=0;ks<12;ks++){
            u32 ah[2][4],al[2][4],bh[2][4],bl[2][4];
#pragma unroll
            for(int mt=0;mt<2;mt++){ ldsm4(ah[mt],aH+mt*6400+ks*32); ldsm4(al[mt],aL+mt*6400+ks*32); }
#pragma unroll
            for(int nt=0;nt<2;nt++){ ldsm4t(bh[nt],bH+nt*32+ks*2304); ldsm4t(bl[nt],bL+nt*32+ks*2304); }
#pragma unroll
            for(int mt=0;mt<2;mt++)
#pragma unroll
                for(int nf=0;nf<4;nf++){
                    int nt=nf>>1, rp=(nf&1)*2;
                    mma_bf16(acc[mt][nf], ah[mt], bh[nt][rp], bh[nt][rp+1]);
                    mma_bf16(acc[mt][nf], ah[mt], bl[nt][rp], bl[nt][rp+1]);
                    mma_bf16(acc[mt][nf], al[mt], bh[nt][rp], bh[nt][rp+1]);
                }
        }
    }
    // epilogue: split h to bf16 hi/lo, store
    int g=lane>>2, t4=lane&3;
#pragma unroll
    for(int mt=0;mt<2;mt++)
#pragma unroll
        for(int nf=0;nf<4;nf++){
            int w=nh*32+nf*8+2*t4;
#pragma unroll
            for(int rh=0;rh<2;rh++){
                int er=mh*32+mt*16+g+rh*8;
                float v0=acc[mt][nf][rh*2], v1=acc[mt][nf][rh*2+1];
                float h0=bhi(v0), h1=bhi(v1);
                size_t off=((size_t)(b*64+er)*64+(y0+yyw))*64+w;
                *(u32*)(g_hh+off)=pack2(v0,v1);
                *(u32*)(g_hl+off)=pack2(v0-h0,v1-h1);
            }
        }
}

// ---------------- stage 2 ----------------
__global__ __launch_bounds__(256,1) void stage2(float* __restrict__ out){
    extern __shared__ char sm[];
    __nv_bfloat16* As=(__nv_bfloat16*)sm;
    char* Bs=sm+51200;
    const int tid=threadIdx.x, wid=tid>>5, lane=tid&31;
    const int b=blockIdx.x>>5, y0=(blockIdx.x&31)<<1;
    const int yyw=wid>>2, mh=(wid>>1)&1, nh=wid&1;
    const u32 sA=smaddr(As), sB=smaddr(Bs);
    const int lr=lane&7, ls=lane>>3;
    const u32 aLane=(u32)(((ls&1)*8+lr)*400+(ls>>1)*16);
    const u32 bLane=(u32)(((ls&1)*8+lr)*144+(ls>>1)*16);

    // build B once: rows k=er*3+dh <- h rows (zero-padded at y borders)
    for(int i=tid;i<6144;i+=256){
        int row=i>>3, j=i&7;
        int tile=row/192, k=row-tile*192;
        int yy=tile>>1, p=tile&1;
        int er=k/3, dh=k-er*3, ys=y0+yy+dh-1;
        uint4 v=make_uint4(0,0,0,0);
        if((unsigned)ys<64u)
            v=*(const uint4*)((p?g_hl:g_hh)+((size_t)(b*64+er)*64+ys)*64+j*8);
        *(uint4*)(Bs+tile*27648+k*144+j*16)=v;
    }
    int g=lane>>2, t4=lane&3;
    for(int cb=0;cb<4;cb++){
        __syncthreads();
        { const uint4* src=(const uint4*)g_W2img[cb]; uint4* dst=(uint4*)As;
          for(int i=tid;i<3200;i+=256) dst[i]=src[i]; }
        __syncthreads();
        float acc[2][4][4];
#pragma unroll
        for(int i=0;i<2;i++)
#pragma unroll
            for(int j=0;j<4;j++){acc[i][j][0]=0;acc[i][j][1]=0;acc[i][j][2]=0;acc[i][j][3]=0;}
        const u32 aH=sA + (u32)(mh*32*400) + aLane;
        const u32 aL=aH + 64u*400u;
        const u32 bH=sB + (u32)((yyw*2+0)*27648 + nh*64) + bLane;
        const u32 bL=sB + (u32)((yyw*2+1)*27648 + nh*64) + bLane;
#pragma unroll 1
        for(int ks=0;ks<12;ks++){
            u32 ah[2][4],al[2][4],bh[2][4],bl[2][4];
#pragma unroll
            for(int mt=0;mt<2;mt++){ ldsm4(ah[mt],aH+mt*6400+ks*32); ldsm4(al[mt],aL+mt*6400+ks*32); }
#pragma unroll
            for(int nt=0;nt<2;nt++){ ldsm4t(bh[nt],bH+nt*32+ks*2304); ldsm4t(bl[nt],bL+nt*32+ks*2304); }
#pragma unroll
            for(int mt=0;mt<2;mt++)
#pragma unroll
                for(int nf=0;nf<4;nf++){
                    int nt=nf>>1, rp=(nf&1)*2;
                    mma_bf16(acc[mt][nf], ah[mt], bh[nt][rp], bh[nt][rp+1]);
                    mma_bf16(acc[mt][nf], ah[mt], bl[nt][rp], bl[nt][rp+1]);
                    mma_bf16(acc[mt][nf], al[mt], bh[nt][rp], bh[nt][rp+1]);
                }
        }
        // epilogue: fp32 out
#pragma unroll
        for(int mt=0;mt<2;mt++)
#pragma unroll
            for(int nf=0;nf<4;nf++){
                int w=nh*32+nf*8+2*t4;
#pragma unroll
                for(int rh=0;rh<2;rh++){
                    int co=cb*64+mh*32+mt*16+g+rh*8;
                    float2 v2=make_float2(acc[mt][nf][rh*2],acc[mt][nf][rh*2+1]);
                    *(float2*)(out+((size_t)(b*256+co)*64+(y0+yyw))*64+w)=v2;
                }
            }
    }
}

// ---------------------------------------------------------------------------
extern "C" void kernel_launch(void* const* d_in, const int* in_sizes, int n_in,
                              void* d_out, int out_size){
    (void)in_sizes; (void)n_in; (void)out_size;
    const float* x    =(const float*)d_in[0];
    const float* probs=(const float*)d_in[1];
    const float* win  =(const float*)d_in[2];
    const float* wout =(const float*)d_in[3];
    float* out=(float*)d_out;
    cudaFuncSetAttribute(stage1, cudaFuncAttributeMaxDynamicSharedMemorySize, S_SMEM);
    cudaFuncSetAttribute(stage2, cudaFuncAttributeMaxDynamicSharedMemorySize, S_SMEM);
    prep_w1<<<384,256>>>(win);
    prep_w2<<<384,256>>>(wout,probs);
    stage1<<<512,256,S_SMEM>>>(x);
    stage2<<<512,256,S_SMEM>>>(out);
}